// round 15
// baseline (speedup 1.0000x reference)
#include <cuda_runtime.h>
#include <cuda_fp16.h>
#include <math.h>

#define HEADS   16
#define DHEAD   64
#define BATCH   4
#define SEQ     2048
#define DIM     1024
#define INNER   1024
#define TOKENS  (BATCH*SEQ)       /* 8192 */
#define KVLEN   (SEQ+1)           /* 2049; null slot at j=2048 */
#define SCALE_F 8.0f
#define LN_EPS  1e-5f
#define L2_EPS  1e-12f

#define NQKV    (3 * INNER)
#define KTPITCH 2112
#define VROWSP  1056

// ---------------- scratch (global device arrays; no allocations) -------------
__device__ unsigned g_xnH  [TOKENS * DIM / 2];
__device__ unsigned g_WqkvP[(DIM / 2) * NQKV];
__device__ unsigned g_WoP  [(INNER / 2) * DIM];
__device__ unsigned g_QP   [64 * SEQ * 32];
__device__ unsigned g_KtP  [64 * 32 * KTPITCH];
__device__ unsigned g_VtP  [64 * VROWSP * 64];
__device__ unsigned g_aoH  [TOKENS * INNER / 2];

// ---------------- fp16 / async helpers ------------------------------------------
__device__ __forceinline__ void mma_f16(float* c, const unsigned* a, const unsigned* b) {
    asm volatile(
        "mma.sync.aligned.m16n8k16.row.col.f32.f16.f16.f32 "
        "{%0,%1,%2,%3}, {%4,%5,%6,%7}, {%8,%9}, {%0,%1,%2,%3};"
        : "+f"(c[0]), "+f"(c[1]), "+f"(c[2]), "+f"(c[3])
        : "r"(a[0]), "r"(a[1]), "r"(a[2]), "r"(a[3]), "r"(b[0]), "r"(b[1]));
}
__device__ __forceinline__ unsigned pack2(float a, float b) {
    __half2 h2 = __floats2half2_rn(a, b);
    return *(unsigned*)&h2;
}
__device__ __forceinline__ void cp_async16(unsigned smem_addr, const void* gptr) {
    asm volatile("cp.async.cg.shared.global [%0], [%1], 16;"
                 :: "r"(smem_addr), "l"(gptr) : "memory");
}
__device__ __forceinline__ void cp_commit() {
    asm volatile("cp.async.commit_group;" ::: "memory");
}
__device__ __forceinline__ void cp_wait0() {
    asm volatile("cp.async.wait_group 0;" ::: "memory");
}
__device__ __forceinline__ void cp_wait1() {
    asm volatile("cp.async.wait_group 1;" ::: "memory");
}

// ---------------- LayerNorm (writes packed fp16) --------------------------------
__global__ void __launch_bounds__(256) ln_kernel(const float* __restrict__ x,
                                                 const float* __restrict__ gamma,
                                                 const float* __restrict__ beta) {
    __shared__ float red[8][2];
    const int t = blockIdx.x;
    const int i = threadIdx.x;
    const float4 v = ((const float4*)(x + (size_t)t * DIM))[i];
    float s  = v.x + v.y + v.z + v.w;
    float ss = v.x*v.x + v.y*v.y + v.z*v.z + v.w*v.w;
    #pragma unroll
    for (int o = 16; o > 0; o >>= 1) {
        s  += __shfl_xor_sync(0xFFFFFFFFu, s,  o);
        ss += __shfl_xor_sync(0xFFFFFFFFu, ss, o);
    }
    const int w = i >> 5, l = i & 31;
    if (l == 0) { red[w][0] = s; red[w][1] = ss; }
    __syncthreads();
    if (w == 0) {
        s  = (l < 8) ? red[l][0] : 0.f;
        ss = (l < 8) ? red[l][1] : 0.f;
        #pragma unroll
        for (int o = 4; o > 0; o >>= 1) {
            s  += __shfl_xor_sync(0xFFFFFFFFu, s,  o);
            ss += __shfl_xor_sync(0xFFFFFFFFu, ss, o);
        }
        if (l == 0) { red[0][0] = s; red[0][1] = ss; }
    }
    __syncthreads();
    const float mu   = red[0][0] * (1.f / DIM);
    const float var  = red[0][1] * (1.f / DIM) - mu * mu;
    const float rstd = rsqrtf(var + LN_EPS);
    const float4 g  = ((const float4*)gamma)[i];
    const float4 be = ((const float4*)beta)[i];
    float4 o4;
    o4.x = (v.x - mu) * rstd * g.x + be.x;
    o4.y = (v.y - mu) * rstd * g.y + be.y;
    o4.z = (v.z - mu) * rstd * g.z + be.z;
    o4.w = (v.w - mu) * rstd * g.w + be.w;
    const size_t wi = (size_t)t * (DIM / 2) + 2 * i;
    *(uint2*)&g_xnH[wi] = make_uint2(pack2(o4.x, o4.y), pack2(o4.z, o4.w));
}

// ---------------- weight packing -------------------------------------------------
__global__ void __launch_bounds__(256) pack_qkv(const float* __restrict__ Wq,
                                                const float* __restrict__ Wkv) {
    const int total = (DIM / 2) * NQKV;
    for (int idx = blockIdx.x * 256 + threadIdx.x; idx < total; idx += gridDim.x * 256) {
        const int kp = idx / NQKV;
        const int n  = idx - kp * NQKV;
        float a, b;
        if (n < INNER) {
            a = Wq[(size_t)(2 * kp) * INNER + n];
            b = Wq[(size_t)(2 * kp + 1) * INNER + n];
        } else {
            const int nk = (n < 2 * INNER) ? (n - INNER) : (n - 2 * INNER + INNER);
            a = Wkv[(size_t)(2 * kp) * (2 * INNER) + nk];
            b = Wkv[(size_t)(2 * kp + 1) * (2 * INNER) + nk];
        }
        g_WqkvP[idx] = pack2(a, b);
    }
}
__global__ void __launch_bounds__(256) pack_w(const float* __restrict__ W,
                                              unsigned* __restrict__ WP,
                                              int K, int N) {
    const int total = (K / 2) * N;
    for (int idx = blockIdx.x * 256 + threadIdx.x; idx < total; idx += gridDim.x * 256) {
        const int kp = idx / N;
        const int n  = idx - kp * N;
        WP[idx] = pack2(W[(size_t)(2 * kp) * N + n], W[(size_t)(2 * kp + 1) * N + n]);
    }
}

// ---------------- fp16 single-pass GEMM mainloop (k64 chunks, 3-stage) ----------
#define ASLD 36      /* A row stride (words), 32 used */
#define BSLD 136     /* B row stride (words), 128 used */
#define GSTAGE_W (128 * ASLD + 32 * BSLD)    /* 8960 words per stage */
#define GEMM_SMEM (3 * GSTAGE_W * 4)         /* 107520 B */

#define GEMM_MAINLOOP(AH, BP, N, K)                                               \
    extern __shared__ unsigned gsm[];                                             \
    const unsigned gsb = (unsigned)__cvta_generic_to_shared(gsm);                 \
    const int tid  = threadIdx.x;                                                 \
    const int warp = tid >> 5;                                                    \
    const int lane = tid & 31;                                                    \
    const int r = lane >> 2;                                                      \
    const int c = lane & 3;                                                       \
    const int wm = (warp & 3) * 32;                                               \
    const int wn = (warp >> 2) * 64;                                              \
    const int rowBase = blockIdx.y * 128;                                         \
    const int colBase = blockIdx.x * 128;                                         \
    const int arow = tid >> 1;                                                    \
    const int asel = (tid & 1) * 16;                                              \
    const int bkp  = tid >> 3;                                                    \
    const int bn0  = (tid & 7) * 16;                                              \
    const unsigned* ApH = (AH) + (size_t)(rowBase + arow) * ((K) / 2) + asel;     \
    const unsigned* BpP = (BP) + colBase + bn0;                                   \
    float acc[2][8][4];                                                           \
    _Pragma("unroll")                                                             \
    for (int mi = 0; mi < 2; mi++)                                                \
        _Pragma("unroll")                                                         \
        for (int ni = 0; ni < 8; ni++)                                            \
            _Pragma("unroll")                                                     \
            for (int j = 0; j < 4; j++) acc[mi][ni][j] = 0.f;                     \
    const int NC = (K) / 64;                                                      \
    const unsigned aoff0 = (arow * ASLD + asel) * 4;                              \
    const unsigned boff0 = (128 * ASLD + bkp * BSLD + bn0) * 4;                   \
    auto fill_async = [&](int ck) {                                               \
        const unsigned st = gsb + ((ck % 3) * GSTAGE_W) * 4;                      \
        const int kw = ck * 32;                                                   \
        cp_async16(st + aoff0,      ApH + kw);                                    \
        cp_async16(st + aoff0 + 16, ApH + kw + 4);                                \
        cp_async16(st + aoff0 + 32, ApH + kw + 8);                                \
        cp_async16(st + aoff0 + 48, ApH + kw + 12);                               \
        const unsigned* bp = BpP + (size_t)(kw + bkp) * (N);                      \
        cp_async16(st + boff0,      bp);                                          \
        cp_async16(st + boff0 + 16, bp + 4);                                      \
        cp_async16(st + boff0 + 32, bp + 8);                                      \
        cp_async16(st + boff0 + 48, bp + 12);                                     \
    };                                                                            \
    fill_async(0);                                                                \
    cp_commit();                                                                  \
    fill_async(1);                                                                \
    cp_commit();                                                                  \
    _Pragma("unroll 1")                                                           \
    for (int ck = 0; ck < NC; ck++) {                                             \
        if (ck + 1 < NC) cp_wait1(); else cp_wait0();                             \
        __syncthreads();                                                          \
        if (ck + 2 < NC) { fill_async(ck + 2); cp_commit(); }                     \
        const unsigned* st  = gsm + (ck % 3) * GSTAGE_W;                          \
        const unsigned* AsH = st;                                                 \
        const unsigned* Bs  = st + 128 * ASLD;                                    \
        _Pragma("unroll")                                                         \
        for (int s = 0; s < 4; s++) {                                             \
            unsigned ah[2][4];                                                    \
            _Pragma("unroll")                                                     \
            for (int mi = 0; mi < 2; mi++) {                                      \
                const int row = wm + mi * 16;                                     \
                ah[mi][0] = AsH[(row + r) * ASLD + 8 * s + c];                    \
                ah[mi][1] = AsH[(row + 8 + r) * ASLD + 8 * s + c];                \
                ah[mi][2] = AsH[(row + r) * ASLD + 8 * s + c + 4];                \
                ah[mi][3] = AsH[(row + 8 + r) * ASLD + 8 * s + c + 4];            \
            }                                                                     \
            _Pragma("unroll")                                                     \
            for (int ni = 0; ni < 8; ni++) {                                      \
                unsigned bf[2];                                                   \
                bf[0] = Bs[(8 * s + c) * BSLD + wn + ni * 8 + r];                 \
                bf[1] = Bs[(8 * s + c + 4) * BSLD + wn + ni * 8 + r];             \
                _Pragma("unroll")                                                 \
                for (int mi = 0; mi < 2; mi++)                                    \
                    mma_f16(acc[mi][ni], ah[mi], bf);                             \
            }                                                                     \
        }                                                                         \
    }

// ---- fused q|k|v projection: epilogue dispatch by column range -----------------
__global__ void __launch_bounds__(256, 2) gemm_qkv_kernel(const float* __restrict__ q_scale,
                                                          const float* __restrict__ k_scale) {
    GEMM_MAINLOOP(g_xnH, g_WqkvP, NQKV, DIM)
    const int nbase = colBase + wn;
    if (nbase < INNER) {
        const int h = nbase >> 6;
        #pragma unroll
        for (int mi = 0; mi < 2; mi++) {
            const int row0 = rowBase + wm + mi * 16 + r;
            float ss0 = 0.f, ss1 = 0.f;
            #pragma unroll
            for (int ni = 0; ni < 8; ni++) {
                ss0 += acc[mi][ni][0] * acc[mi][ni][0] + acc[mi][ni][1] * acc[mi][ni][1];
                ss1 += acc[mi][ni][2] * acc[mi][ni][2] + acc[mi][ni][3] * acc[mi][ni][3];
            }
            ss0 += __shfl_xor_sync(0xFFFFFFFFu, ss0, 1);
            ss0 += __shfl_xor_sync(0xFFFFFFFFu, ss0, 2);
            ss1 += __shfl_xor_sync(0xFFFFFFFFu, ss1, 1);
            ss1 += __shfl_xor_sync(0xFFFFFFFFu, ss1, 2);
            const float f0 = SCALE_F / fmaxf(sqrtf(ss0), L2_EPS);
            const float f1 = SCALE_F / fmaxf(sqrtf(ss1), L2_EPS);
            #pragma unroll
            for (int ni = 0; ni < 8; ni++) {
                const float2 qs = *(const float2*)&q_scale[ni * 8 + 2 * c];
                const int bb0 = row0 >> 11, i0 = row0 & 2047;
                const int bb1 = (row0 + 8) >> 11, i1 = (row0 + 8) & 2047;
                g_QP[((size_t)(bb0 * HEADS + h) * SEQ + i0) * 32 + ni * 4 + c] =
                    pack2(acc[mi][ni][0] * f0 * qs.x, acc[mi][ni][1] * f0 * qs.y);
                g_QP[((size_t)(bb1 * HEADS + h) * SEQ + i1) * 32 + ni * 4 + c] =
                    pack2(acc[mi][ni][2] * f1 * qs.x, acc[mi][ni][3] * f1 * qs.y);
            }
        }
    } else if (nbase < 2 * INNER) {
        const int h = (nbase - INNER) >> 6;
        #pragma unroll
        for (int mi = 0; mi < 2; mi++) {
            const int row0 = rowBase + wm + mi * 16 + r;
            float ss0 = 0.f, ss1 = 0.f;
            #pragma unroll
            for (int ni = 0; ni < 8; ni++) {
                ss0 += acc[mi][ni][0] * acc[mi][ni][0] + acc[mi][ni][1] * acc[mi][ni][1];
                ss1 += acc[mi][ni][2] * acc[mi][ni][2] + acc[mi][ni][3] * acc[mi][ni][3];
            }
            ss0 += __shfl_xor_sync(0xFFFFFFFFu, ss0, 1);
            ss0 += __shfl_xor_sync(0xFFFFFFFFu, ss0, 2);
            ss1 += __shfl_xor_sync(0xFFFFFFFFu, ss1, 1);
            ss1 += __shfl_xor_sync(0xFFFFFFFFu, ss1, 2);
            const float f0 = 1.f / fmaxf(sqrtf(ss0), L2_EPS);
            const float f1 = 1.f / fmaxf(sqrtf(ss1), L2_EPS);
            #pragma unroll
            for (int ni = 0; ni < 8; ni++) {
                const float2 ks = *(const float2*)&k_scale[ni * 8 + 2 * c];
                const int dd = ni * 4 + c;
                const int bb0 = row0 >> 11, i0 = row0 & 2047;
                const int bb1 = (row0 + 8) >> 11, i1 = (row0 + 8) & 2047;
                g_KtP[((size_t)(bb0 * HEADS + h) * 32 + dd) * KTPITCH + i0] =
                    pack2(acc[mi][ni][0] * f0 * ks.x, acc[mi][ni][1] * f0 * ks.y);
                g_KtP[((size_t)(bb1 * HEADS + h) * 32 + dd) * KTPITCH + i1] =
                    pack2(acc[mi][ni][2] * f1 * ks.x, acc[mi][ni][3] * f1 * ks.y);
            }
        }
    } else {
        const int h = (nbase - 2 * INNER) >> 6;
        const bool evenr = ((lane >> 2) & 1) == 0;
        #pragma unroll
        for (int mi = 0; mi < 2; mi++) {
            const int row0 = rowBase + wm + mi * 16 + r;
            #pragma unroll
            for (int ni = 0; ni < 8; ni++) {
                const float p0 = __shfl_xor_sync(0xFFFFFFFFu, acc[mi][ni][0], 4);
                const float p1 = __shfl_xor_sync(0xFFFFFFFFu, acc[mi][ni][1], 4);
                const float p2 = __shfl_xor_sync(0xFFFFFFFFu, acc[mi][ni][2], 4);
                const float p3 = __shfl_xor_sync(0xFFFFFFFFu, acc[mi][ni][3], 4);
                if (evenr) {
                    const int bb = row0 >> 11;
                    const int i0 = row0 & 2047;
                    const int jj = i0 >> 1;
                    const int d0 = ni * 8 + 2 * c;
                    unsigned* base = g_VtP + (size_t)(bb * HEADS + h) * VROWSP * 64;
                    *(uint2*)&base[(size_t)jj * 64 + d0] =
                        make_uint2(pack2(acc[mi][ni][0], p0), pack2(acc[mi][ni][1], p1));
                    *(uint2*)&base[(size_t)(jj + 4) * 64 + d0] =
                        make_uint2(pack2(acc[mi][ni][2], p2), pack2(acc[mi][ni][3], p3));
                }
            }
        }
    }
}

// ---- output projection ----
__global__ void __launch_bounds__(256, 2) gemm_o_kernel(float* __restrict__ out) {
    GEMM_MAINLOOP(g_aoH, g_WoP, DIM, INNER)
    #pragma unroll
    for (int mi = 0; mi < 2; mi++) {
        const int row = rowBase + wm + mi * 16 + r;
        #pragma unroll
        for (int ni = 0; ni < 8; ni++) {
            const int col = colBase + wn + ni * 8 + 2 * c;
            *(float2*)&out[(size_t)row * DIM + col]       = make_float2(acc[mi][ni][0], acc[mi][ni][1]);
            *(float2*)&out[(size_t)(row + 8) * DIM + col] = make_float2(acc[mi][ni][2], acc[mi][ni][3]);
        }
    }
}

// ---------------- null slot at j=2048 -------------------------------------------
__global__ void null_prep(const float* __restrict__ null_kv,
                          const float* __restrict__ k_scale) {
    const int bh = blockIdx.x;
    const int h = bh & 15;
    const int lane = threadIdx.x;
    const int src0 = (2 * lane) & 31;
    const int src1 = (2 * lane + 1) & 31;
    const float* nk = null_kv + h * DHEAD;
    const float* nv = null_kv + HEADS * DHEAD + h * DHEAD;
    float k0 = nk[lane], k1 = nk[lane + 32];
    float ss = k0 * k0 + k1 * k1;
    #pragma unroll
    for (int o = 16; o > 0; o >>= 1) ss += __shfl_xor_sync(0xFFFFFFFFu, ss, o);
    const float inv = 1.f / fmaxf(sqrtf(ss), L2_EPS);
    const float kk0 = k0 * inv * k_scale[lane];
    const float kk1 = k1 * inv * k_scale[lane + 32];
    {
        float s0a = __shfl_sync(0xFFFFFFFFu, kk0, src0);
        float s0b = __shfl_sync(0xFFFFFFFFu, kk0, src1);
        float s1a = __shfl_sync(0xFFFFFFFFu, kk1, src0);
        float s1b = __shfl_sync(0xFFFFFFFFu, kk1, src1);
        const float a = (lane < 16) ? s0a : s1a;
        const float b = (lane < 16) ? s0b : s1b;
        g_KtP[((size_t)bh * 32 + lane) * KTPITCH + 2048] = pack2(a, b);
    }
    const float v0 = nv[lane], v1 = nv[lane + 32];
    unsigned* base = g_VtP + ((size_t)bh * VROWSP + 1024) * 64;
    base[lane]      = pack2(v0, 0.f);
    base[lane + 32] = pack2(v1, 0.f);
}

// ---------------- flash attention: 3-stage cp.async fills -----------------------
#define ABQ 128
#define ABK 64
#define ANT ((KVLEN + ABK - 1) / ABK)   /* 33 */
#define KTLD 72
#define VLD  72
#define AST_W (32 * KTLD + 32 * VLD)    /* 4608 words per stage */

#define ATT_SMEM (3 * AST_W * 4)        /* 55296 B */

__global__ void __launch_bounds__(256, 2) attn_mma_kernel() {
    extern __shared__ unsigned ash[];
    const unsigned asb = (unsigned)__cvta_generic_to_shared(ash);

    const int tid  = threadIdx.x;
    const int warp = tid >> 5;
    const int lane = tid & 31;
    const int r = lane >> 2;
    const int c = lane & 3;
    const int bh = blockIdx.y;
    const int qt = blockIdx.x;
    const int m0 = warp * 16;

    const unsigned* QgP = g_QP + ((size_t)bh * SEQ + (size_t)qt * ABQ + m0) * 32;
    unsigned qh[4][4];
    #pragma unroll
    for (int s = 0; s < 4; s++) {
        qh[s][0] = QgP[(size_t)r * 32 + s * 8 + c];
        qh[s][1] = QgP[(size_t)(r + 8) * 32 + s * 8 + c];
        qh[s][2] = QgP[(size_t)r * 32 + s * 8 + c + 4];
        qh[s][3] = QgP[(size_t)(r + 8) * 32 + s * 8 + c + 4];
    }

    float oacc[8][4];
    #pragma unroll
    for (int nt = 0; nt < 8; nt++)
        #pragma unroll
        for (int j = 0; j < 4; j++) oacc[nt][j] = 0.f;
    float mrow0 = -1e30f, mrow1 = -1e30f, lrow0 = 0.f, lrow1 = 0.f;

    const unsigned* KtG = g_KtP + ((size_t)bh * 32 + (tid >> 3)) * KTPITCH + (tid & 7) * 8;
    const unsigned* VtG = g_VtP + ((size_t)bh * VROWSP + (tid >> 3)) * 64 + (tid & 7) * 8;
    const unsigned koff = ((tid >> 3) * KTLD + (tid & 7) * 8) * 4;
    const unsigned voff = (32 * KTLD + (tid >> 3) * VLD + (tid & 7) * 8) * 4;

    auto fill_async = [&](int kt) {
        const unsigned st = asb + ((kt % 3) * AST_W) * 4;
        const int kvbase = kt * ABK;
        cp_async16(st + koff,      KtG + kvbase);
        cp_async16(st + koff + 16, KtG + kvbase + 4);
        const unsigned* vp = VtG + (size_t)(kt * 32) * 64;
        cp_async16(st + voff,      vp);
        cp_async16(st + voff + 16, vp + 4);
    };

    fill_async(0);
    cp_commit();
    fill_async(1);
    cp_commit();

    for (int kt = 0; kt < ANT; kt++) {
        const int kvbase = kt * ABK;
        if (kt + 1 < ANT) cp_wait1(); else cp_wait0();
        __syncthreads();
        if (kt + 2 < ANT) { fill_async(kt + 2); cp_commit(); }

        const unsigned* KtH = ash + (kt % 3) * AST_W;
        const unsigned* VH  = KtH + 32 * KTLD;

        float sa[8][4];
        #pragma unroll
        for (int nt = 0; nt < 8; nt++)
            #pragma unroll
            for (int j = 0; j < 4; j++) sa[nt][j] = 0.f;

        #pragma unroll
        for (int s = 0; s < 4; s++) {
            #pragma unroll
            for (int nt = 0; nt < 8; nt++) {
                unsigned bfh[2];
                bfh[0] = KtH[(8 * s + c) * KTLD + nt * 8 + r];
                bfh[1] = KtH[(8 * s + c + 4) * KTLD + nt * 8 + r];
                mma_f16(sa[nt], qh[s], bfh);
            }
        }

        float tmax0 = -1e30f, tmax1 = -1e30f;
        #pragma unroll
        for (int nt = 0; nt < 8; nt++) {
            const int j0 = kvbase + nt * 8 + 2 * c;
            if (j0 >= KVLEN)     { sa[nt][0] = -1e30f; sa[nt][2] = -1e30f; }
            if (j0 + 1 >= KVLEN) { sa[nt][1] = -1e30f; sa[nt][3] = -1e30f; }
            tmax0 = fmaxf(tmax0, fmaxf(sa[nt][0], sa[nt][1]));
            tmax1 = fmaxf(tmax1, fmaxf(sa[nt][2], sa[nt][3]));
        }
        tmax0 = fmaxf(tmax0, __shfl_xor_sync(0xFFFFFFFFu, tmax0, 1));
        tmax0 = fmaxf(tmax0, __shfl_xor_sync(0xFFFFFFFFu, tmax0, 2));
        tmax1 = fmaxf(tmax1, __shfl_xor_sync(0xFFFFFFFFu, tmax1, 1));
        tmax1 = fmaxf(tmax1, __shfl_xor_sync(0xFFFFFFFFu, tmax1, 2));

        const float mnew0 = fmaxf(mrow0, tmax0);
        const float mnew1 = fmaxf(mrow1, tmax1);
        const float cf0 = __expf(mrow0 - mnew0);
        const float cf1 = __expf(mrow1 - mnew1);
        mrow0 = mnew0; mrow1 = mnew1;

        unsigned pfrag[8][2];
        float psum0 = 0.f, psum1 = 0.f;
        #pragma unroll
        for (int nt = 0; nt < 8; nt++) {
            const float p0 = __expf(sa[nt][0] - mnew0);
            const float p1 = __expf(sa[nt][1] - mnew0);
            const float p2 = __expf(sa[nt][2] - mnew1);
            const float p3 = __expf(sa[nt][3] - mnew1);
            psum0 += p0 + p1;
            psum1 += p2 + p3;
            pfrag[nt][0] = pack2(p0, p1);
            pfrag[nt][1] = pack2(p2, p3);
        }
        psum0 += __shfl_xor_sync(0xFFFFFFFFu, psum0, 1);
        psum0 += __shfl_xor_sync(0xFFFFFFFFu, psum0, 2);
        psum1 += __shfl_xor_sync(0xFFFFFFFFu, psum1, 1);
        psum1 += __shfl_xor_sync(0xFFFFFFFFu, psum1, 2);
        lrow0 = lrow0 * cf0 + psum0;
        lrow1 = lrow1 * cf1 + psum1;

        #pragma unroll
        for (int nt = 0; nt < 8; nt++) {
            oacc[nt][0] *= cf0; oacc[nt][1] *= cf0;
            oacc[nt][2] *= cf1; oacc[nt][3] *= cf1;
        }

        #pragma unroll
        for (int s = 0; s < 4; s++) {
            unsigned pa[4];
            pa[0] = pfrag[2 * s][0];
            pa[1] = pfrag[2 * s][1];
            pa[2] = pfrag[2 * s + 1][0];
            pa[3] = pfrag[2 * s + 1][1];
            #pragma unroll
            for (int nt = 0; nt < 8; nt++) {
                unsigned vfh[2];
                vfh[0] = VH[(8 * s + c) * VLD + nt * 8 + r];
                vfh[1] = VH[(8 * s + c + 4) * VLD + nt * 8 + r];
                mma_f16(oacc[nt], pa, vfh);
            }
        }
    }

    const float li0 = 1.f / lrow0;
    const float li1 = 1.f / lrow1;
    const int bb = bh >> 4, h = bh & 15;
    const int row0 = qt * ABQ + m0 + r;
    #pragma unroll
    for (int nt = 0; nt < 8; nt++) {
        const size_t wi0 = (size_t)(bb * SEQ + row0) * (INNER / 2) + h * 32 + nt * 4 + c;
        const size_t wi1 = (size_t)(bb * SEQ + row0 + 8) * (INNER / 2) + h * 32 + nt * 4 + c;
        g_aoH[wi0] = pack2(oacc[nt][0] * li0, oacc[nt][1] * li0);
        g_aoH[wi1] = pack2(oacc[nt][2] * li1, oacc[nt][3] * li1);
    }
}

// ---------------- launch ------------------------------------------------------
extern "C" void kernel_launch(void* const* d_in, const int* in_sizes, int n_in,
                              void* d_out, int out_size) {
    const float* x       = (const float*)d_in[0];
    const float* gamma   = (const float*)d_in[1];
    const float* beta    = (const float*)d_in[2];
    const float* null_kv = (const float*)d_in[3];
    const float* Wq      = (const float*)d_in[4];
    const float* Wkv     = (const float*)d_in[5];
    const float* q_scale = (const float*)d_in[6];
    const float* k_scale = (const float*)d_in[7];
    const float* Wo      = (const float*)d_in[8];
    float* out = (float*)d_out;

    unsigned* wop;
    cudaGetSymbolAddress((void**)&wop, g_WoP);

    cudaFuncSetAttribute(gemm_qkv_kernel, cudaFuncAttributeMaxDynamicSharedMemorySize, GEMM_SMEM);
    cudaFuncSetAttribute(gemm_o_kernel,   cudaFuncAttributeMaxDynamicSharedMemorySize, GEMM_SMEM);
    cudaFuncSetAttribute(attn_mma_kernel, cudaFuncAttributeMaxDynamicSharedMemorySize, ATT_SMEM);

    pack_qkv<<<768, 256>>>(Wq, Wkv);
    pack_w<<<512, 256>>>(Wo, wop, INNER, DIM);
    ln_kernel<<<TOKENS, 256>>>(x, gamma, beta);
    null_prep<<<BATCH * HEADS, 32>>>(null_kv, k_scale);
    gemm_qkv_kernel<<<dim3(NQKV / 128, TOKENS / 128), 256, GEMM_SMEM>>>(q_scale, k_scale);
    attn_mma_kernel<<<dim3(SEQ / ABQ, BATCH * HEADS), 256, ATT_SMEM>>>();
    gemm_o_kernel<<<dim3(DIM / 128, TOKENS / 128), 256, GEMM_SMEM>>>(out);
}

// round 16
// speedup vs baseline: 1.0912x; 1.0912x over previous
#include <cuda_runtime.h>
#include <cuda_fp16.h>
#include <math.h>

#define HEADS   16
#define DHEAD   64
#define BATCH   4
#define SEQ     2048
#define DIM     1024
#define INNER   1024
#define TOKENS  (BATCH*SEQ)       /* 8192 */
#define KVLEN   (SEQ+1)           /* 2049; null slot at j=2048 */
#define SCALE_F 8.0f
#define LN_EPS  1e-5f
#define L2_EPS  1e-12f

#define NQKV    (3 * INNER)
#define KTPITCH 2112
#define VROWSP  1056

// ---------------- scratch (global device arrays; no allocations) -------------
__device__ unsigned g_xnH  [TOKENS * DIM / 2];
__device__ unsigned g_WqkvP[(DIM / 2) * NQKV];
__device__ unsigned g_WoP  [(INNER / 2) * DIM];
__device__ unsigned g_QP   [64 * SEQ * 32];
__device__ unsigned g_KtP  [64 * 32 * KTPITCH];
__device__ unsigned g_VtP  [64 * VROWSP * 64];
__device__ unsigned g_aoH  [TOKENS * INNER / 2];

// ---------------- fp16 / async helpers ------------------------------------------
__device__ __forceinline__ void mma_f16(float* c, const unsigned* a, const unsigned* b) {
    asm volatile(
        "mma.sync.aligned.m16n8k16.row.col.f32.f16.f16.f32 "
        "{%0,%1,%2,%3}, {%4,%5,%6,%7}, {%8,%9}, {%0,%1,%2,%3};"
        : "+f"(c[0]), "+f"(c[1]), "+f"(c[2]), "+f"(c[3])
        : "r"(a[0]), "r"(a[1]), "r"(a[2]), "r"(a[3]), "r"(b[0]), "r"(b[1]));
}
__device__ __forceinline__ unsigned pack2(float a, float b) {
    __half2 h2 = __floats2half2_rn(a, b);
    return *(unsigned*)&h2;
}
__device__ __forceinline__ void cp_async16(unsigned smem_addr, const void* gptr) {
    asm volatile("cp.async.cg.shared.global [%0], [%1], 16;"
                 :: "r"(smem_addr), "l"(gptr) : "memory");
}
__device__ __forceinline__ void cp_commit() {
    asm volatile("cp.async.commit_group;" ::: "memory");
}
__device__ __forceinline__ void cp_wait0() {
    asm volatile("cp.async.wait_group 0;" ::: "memory");
}
__device__ __forceinline__ void cp_wait1() {
    asm volatile("cp.async.wait_group 1;" ::: "memory");
}
__device__ __forceinline__ void cp_wait2() {
    asm volatile("cp.async.wait_group 2;" ::: "memory");
}

// ---------------- LayerNorm (writes packed fp16) --------------------------------
__global__ void __launch_bounds__(256) ln_kernel(const float* __restrict__ x,
                                                 const float* __restrict__ gamma,
                                                 const float* __restrict__ beta) {
    __shared__ float red[8][2];
    const int t = blockIdx.x;
    const int i = threadIdx.x;
    const float4 v = ((const float4*)(x + (size_t)t * DIM))[i];
    float s  = v.x + v.y + v.z + v.w;
    float ss = v.x*v.x + v.y*v.y + v.z*v.z + v.w*v.w;
    #pragma unroll
    for (int o = 16; o > 0; o >>= 1) {
        s  += __shfl_xor_sync(0xFFFFFFFFu, s,  o);
        ss += __shfl_xor_sync(0xFFFFFFFFu, ss, o);
    }
    const int w = i >> 5, l = i & 31;
    if (l == 0) { red[w][0] = s; red[w][1] = ss; }
    __syncthreads();
    if (w == 0) {
        s  = (l < 8) ? red[l][0] : 0.f;
        ss = (l < 8) ? red[l][1] : 0.f;
        #pragma unroll
        for (int o = 4; o > 0; o >>= 1) {
            s  += __shfl_xor_sync(0xFFFFFFFFu, s,  o);
            ss += __shfl_xor_sync(0xFFFFFFFFu, ss, o);
        }
        if (l == 0) { red[0][0] = s; red[0][1] = ss; }
    }
    __syncthreads();
    const float mu   = red[0][0] * (1.f / DIM);
    const float var  = red[0][1] * (1.f / DIM) - mu * mu;
    const float rstd = rsqrtf(var + LN_EPS);
    const float4 g  = ((const float4*)gamma)[i];
    const float4 be = ((const float4*)beta)[i];
    float4 o4;
    o4.x = (v.x - mu) * rstd * g.x + be.x;
    o4.y = (v.y - mu) * rstd * g.y + be.y;
    o4.z = (v.z - mu) * rstd * g.z + be.z;
    o4.w = (v.w - mu) * rstd * g.w + be.w;
    const size_t wi = (size_t)t * (DIM / 2) + 2 * i;
    *(uint2*)&g_xnH[wi] = make_uint2(pack2(o4.x, o4.y), pack2(o4.z, o4.w));
}

// ---------------- weight packing (fused: qkv + o) --------------------------------
#define QKV_TOT ((DIM / 2) * NQKV)
#define WO_TOT  ((INNER / 2) * DIM)
__global__ void __launch_bounds__(256) pack_all(const float* __restrict__ Wq,
                                                const float* __restrict__ Wkv,
                                                const float* __restrict__ Wo) {
    const int total = QKV_TOT + WO_TOT;
    for (int idx = blockIdx.x * 256 + threadIdx.x; idx < total; idx += gridDim.x * 256) {
        if (idx < QKV_TOT) {
            const int kp = idx / NQKV;
            const int n  = idx - kp * NQKV;
            float a, b;
            if (n < INNER) {
                a = Wq[(size_t)(2 * kp) * INNER + n];
                b = Wq[(size_t)(2 * kp + 1) * INNER + n];
            } else {
                const int nk = (n < 2 * INNER) ? (n - INNER) : (n - 2 * INNER + INNER);
                a = Wkv[(size_t)(2 * kp) * (2 * INNER) + nk];
                b = Wkv[(size_t)(2 * kp + 1) * (2 * INNER) + nk];
            }
            g_WqkvP[idx] = pack2(a, b);
        } else {
            const int j  = idx - QKV_TOT;
            const int kp = j / DIM;
            const int n  = j - kp * DIM;
            g_WoP[j] = pack2(Wo[(size_t)(2 * kp) * DIM + n], Wo[(size_t)(2 * kp + 1) * DIM + n]);
        }
    }
}

// ---------------- fp16 single-pass GEMM mainloop (k32 chunks, 4-stage) ----------
#define ASLD 20
#define BSLD 136
#define GSTAGE_W (128 * ASLD + 16 * BSLD)    /* 4736 words per stage */
#define GEMM_SMEM (4 * GSTAGE_W * 4)         /* 75776 B */

#define GEMM_MAINLOOP(AH, BP, N, K)                                               \
    extern __shared__ unsigned gsm[];                                             \
    const unsigned gsb = (unsigned)__cvta_generic_to_shared(gsm);                 \
    const int tid  = threadIdx.x;                                                 \
    const int warp = tid >> 5;                                                    \
    const int lane = tid & 31;                                                    \
    const int r = lane >> 2;                                                      \
    const int c = lane & 3;                                                       \
    const int wm = (warp & 3) * 32;                                               \
    const int wn = (warp >> 2) * 64;                                              \
    const int rowBase = blockIdx.y * 128;                                         \
    const int colBase = blockIdx.x * 128;                                         \
    const int arow = tid >> 1;                                                    \
    const int asel = (tid & 1) * 8;                                               \
    const int bkp  = tid >> 4;                                                    \
    const int bn0  = (tid & 15) * 8;                                              \
    const unsigned* ApH = (AH) + (size_t)(rowBase + arow) * ((K) / 2) + asel;     \
    const unsigned* BpP = (BP) + colBase + bn0;                                   \
    float acc[2][8][4];                                                           \
    _Pragma("unroll")                                                             \
    for (int mi = 0; mi < 2; mi++)                                                \
        _Pragma("unroll")                                                         \
        for (int ni = 0; ni < 8; ni++)                                            \
            _Pragma("unroll")                                                     \
            for (int j = 0; j < 4; j++) acc[mi][ni][j] = 0.f;                     \
    const int NC = (K) / 32;                                                      \
    const unsigned aoff0 = (arow * ASLD + asel) * 4;                              \
    const unsigned boff0 = (128 * ASLD + bkp * BSLD + bn0) * 4;                   \
    auto fill_async = [&](int ck) {                                               \
        const unsigned st = gsb + ((ck & 3) * GSTAGE_W) * 4;                      \
        const int kw = ck * 16;                                                   \
        cp_async16(st + aoff0,      ApH + kw);                                    \
        cp_async16(st + aoff0 + 16, ApH + kw + 4);                                \
        const unsigned* bp = BpP + (size_t)(kw + bkp) * (N);                      \
        cp_async16(st + boff0,      bp);                                          \
        cp_async16(st + boff0 + 16, bp + 4);                                      \
    };                                                                            \
    fill_async(0);                                                                \
    cp_commit();                                                                  \
    fill_async(1);                                                                \
    cp_commit();                                                                  \
    fill_async(2);                                                                \
    cp_commit();                                                                  \
    _Pragma("unroll 1")                                                           \
    for (int ck = 0; ck < NC; ck++) {                                             \
        if (ck + 2 < NC) cp_wait2();                                              \
        else if (ck + 1 < NC) cp_wait1();                                         \
        else cp_wait0();                                                          \
        __syncthreads();                                                          \
        if (ck + 3 < NC) { fill_async(ck + 3); cp_commit(); }                     \
        const unsigned* st  = gsm + (ck & 3) * GSTAGE_W;                          \
        const unsigned* AsH = st;                                                 \
        const unsigned* Bs  = st + 128 * ASLD;                                    \
        _Pragma("unroll")                                                         \
        for (int s = 0; s < 2; s++) {                                             \
            unsigned ah[2][4];                                                    \
            _Pragma("unroll")                                                     \
            for (int mi = 0; mi < 2; mi++) {                                      \
                const int row = wm + mi * 16;                                     \
                ah[mi][0] = AsH[(row + r) * ASLD + 8 * s + c];                    \
                ah[mi][1] = AsH[(row + 8 + r) * ASLD + 8 * s + c];                \
                ah[mi][2] = AsH[(row + r) * ASLD + 8 * s + c + 4];                \
                ah[mi][3] = AsH[(row + 8 + r) * ASLD + 8 * s + c + 4];            \
            }                                                                     \
            _Pragma("unroll")                                                     \
            for (int ni = 0; ni < 8; ni++) {                                      \
                unsigned bf[2];                                                   \
                bf[0] = Bs[(8 * s + c) * BSLD + wn + ni * 8 + r];                 \
                bf[1] = Bs[(8 * s + c + 4) * BSLD + wn + ni * 8 + r];             \
                _Pragma("unroll")                                                 \
                for (int mi = 0; mi < 2; mi++)                                    \
                    mma_f16(acc[mi][ni], ah[mi], bf);                             \
            }                                                                     \
        }                                                                         \
    }

// ---- fused q|k|v projection: epilogue dispatch by column range -----------------
__global__ void __launch_bounds__(256, 2) gemm_qkv_kernel(const float* __restrict__ q_scale,
                                                          const float* __restrict__ k_scale) {
    GEMM_MAINLOOP(g_xnH, g_WqkvP, NQKV, DIM)
    const int nbase = colBase + wn;
    if (nbase < INNER) {
        const int h = nbase >> 6;
        #pragma unroll
        for (int mi = 0; mi < 2; mi++) {
            const int row0 = rowBase + wm + mi * 16 + r;
            float ss0 = 0.f, ss1 = 0.f;
            #pragma unroll
            for (int ni = 0; ni < 8; ni++) {
                ss0 += acc[mi][ni][0] * acc[mi][ni][0] + acc[mi][ni][1] * acc[mi][ni][1];
                ss1 += acc[mi][ni][2] * acc[mi][ni][2] + acc[mi][ni][3] * acc[mi][ni][3];
            }
            ss0 += __shfl_xor_sync(0xFFFFFFFFu, ss0, 1);
            ss0 += __shfl_xor_sync(0xFFFFFFFFu, ss0, 2);
            ss1 += __shfl_xor_sync(0xFFFFFFFFu, ss1, 1);
            ss1 += __shfl_xor_sync(0xFFFFFFFFu, ss1, 2);
            const float f0 = SCALE_F / fmaxf(sqrtf(ss0), L2_EPS);
            const float f1 = SCALE_F / fmaxf(sqrtf(ss1), L2_EPS);
            #pragma unroll
            for (int ni = 0; ni < 8; ni++) {
                const float2 qs = *(const float2*)&q_scale[ni * 8 + 2 * c];
                const int bb0 = row0 >> 11, i0 = row0 & 2047;
                const int bb1 = (row0 + 8) >> 11, i1 = (row0 + 8) & 2047;
                g_QP[((size_t)(bb0 * HEADS + h) * SEQ + i0) * 32 + ni * 4 + c] =
                    pack2(acc[mi][ni][0] * f0 * qs.x, acc[mi][ni][1] * f0 * qs.y);
                g_QP[((size_t)(bb1 * HEADS + h) * SEQ + i1) * 32 + ni * 4 + c] =
                    pack2(acc[mi][ni][2] * f1 * qs.x, acc[mi][ni][3] * f1 * qs.y);
            }
        }
    } else if (nbase < 2 * INNER) {
        const int h = (nbase - INNER) >> 6;
        #pragma unroll
        for (int mi = 0; mi < 2; mi++) {
            const int row0 = rowBase + wm + mi * 16 + r;
            float ss0 = 0.f, ss1 = 0.f;
            #pragma unroll
            for (int ni = 0; ni < 8; ni++) {
                ss0 += acc[mi][ni][0] * acc[mi][ni][0] + acc[mi][ni][1] * acc[mi][ni][1];
                ss1 += acc[mi][ni][2] * acc[mi][ni][2] + acc[mi][ni][3] * acc[mi][ni][3];
            }
            ss0 += __shfl_xor_sync(0xFFFFFFFFu, ss0, 1);
            ss0 += __shfl_xor_sync(0xFFFFFFFFu, ss0, 2);
            ss1 += __shfl_xor_sync(0xFFFFFFFFu, ss1, 1);
            ss1 += __shfl_xor_sync(0xFFFFFFFFu, ss1, 2);
            const float f0 = 1.f / fmaxf(sqrtf(ss0), L2_EPS);
            const float f1 = 1.f / fmaxf(sqrtf(ss1), L2_EPS);
            #pragma unroll
            for (int ni = 0; ni < 8; ni++) {
                const float2 ks = *(const float2*)&k_scale[ni * 8 + 2 * c];
                const int dd = ni * 4 + c;
                const int bb0 = row0 >> 11, i0 = row0 & 2047;
                const int bb1 = (row0 + 8) >> 11, i1 = (row0 + 8) & 2047;
                g_KtP[((size_t)(bb0 * HEADS + h) * 32 + dd) * KTPITCH + i0] =
                    pack2(acc[mi][ni][0] * f0 * ks.x, acc[mi][ni][1] * f0 * ks.y);
                g_KtP[((size_t)(bb1 * HEADS + h) * 32 + dd) * KTPITCH + i1] =
                    pack2(acc[mi][ni][2] * f1 * ks.x, acc[mi][ni][3] * f1 * ks.y);
            }
        }
    } else {
        const int h = (nbase - 2 * INNER) >> 6;
        const bool evenr = ((lane >> 2) & 1) == 0;
        #pragma unroll
        for (int mi = 0; mi < 2; mi++) {
            const int row0 = rowBase + wm + mi * 16 + r;
            #pragma unroll
            for (int ni = 0; ni < 8; ni++) {
                const float p0 = __shfl_xor_sync(0xFFFFFFFFu, acc[mi][ni][0], 4);
                const float p1 = __shfl_xor_sync(0xFFFFFFFFu, acc[mi][ni][1], 4);
                const float p2 = __shfl_xor_sync(0xFFFFFFFFu, acc[mi][ni][2], 4);
                const float p3 = __shfl_xor_sync(0xFFFFFFFFu, acc[mi][ni][3], 4);
                if (evenr) {
                    const int bb = row0 >> 11;
                    const int i0 = row0 & 2047;
                    const int jj = i0 >> 1;
                    const int d0 = ni * 8 + 2 * c;
                    unsigned* base = g_VtP + (size_t)(bb * HEADS + h) * VROWSP * 64;
                    *(uint2*)&base[(size_t)jj * 64 + d0] =
                        make_uint2(pack2(acc[mi][ni][0], p0), pack2(acc[mi][ni][1], p1));
                    *(uint2*)&base[(size_t)(jj + 4) * 64 + d0] =
                        make_uint2(pack2(acc[mi][ni][2], p2), pack2(acc[mi][ni][3], p3));
                }
            }
        }
    }
}

// ---- output projection ----
__global__ void __launch_bounds__(256, 2) gemm_o_kernel(float* __restrict__ out) {
    GEMM_MAINLOOP(g_aoH, g_WoP, DIM, INNER)
    #pragma unroll
    for (int mi = 0; mi < 2; mi++) {
        const int row = rowBase + wm + mi * 16 + r;
        #pragma unroll
        for (int ni = 0; ni < 8; ni++) {
            const int col = colBase + wn + ni * 8 + 2 * c;
            *(float2*)&out[(size_t)row * DIM + col]       = make_float2(acc[mi][ni][0], acc[mi][ni][1]);
            *(float2*)&out[(size_t)(row + 8) * DIM + col] = make_float2(acc[mi][ni][2], acc[mi][ni][3]);
        }
    }
}

// ---------------- null slot at j=2048 -------------------------------------------
__global__ void null_prep(const float* __restrict__ null_kv,
                          const float* __restrict__ k_scale) {
    const int bh = blockIdx.x;
    const int h = bh & 15;
    const int lane = threadIdx.x;
    const int src0 = (2 * lane) & 31;
    const int src1 = (2 * lane + 1) & 31;
    const float* nk = null_kv + h * DHEAD;
    const float* nv = null_kv + HEADS * DHEAD + h * DHEAD;
    float k0 = nk[lane], k1 = nk[lane + 32];
    float ss = k0 * k0 + k1 * k1;
    #pragma unroll
    for (int o = 16; o > 0; o >>= 1) ss += __shfl_xor_sync(0xFFFFFFFFu, ss, o);
    const float inv = 1.f / fmaxf(sqrtf(ss), L2_EPS);
    const float kk0 = k0 * inv * k_scale[lane];
    const float kk1 = k1 * inv * k_scale[lane + 32];
    {
        float s0a = __shfl_sync(0xFFFFFFFFu, kk0, src0);
        float s0b = __shfl_sync(0xFFFFFFFFu, kk0, src1);
        float s1a = __shfl_sync(0xFFFFFFFFu, kk1, src0);
        float s1b = __shfl_sync(0xFFFFFFFFu, kk1, src1);
        const float a = (lane < 16) ? s0a : s1a;
        const float b = (lane < 16) ? s0b : s1b;
        g_KtP[((size_t)bh * 32 + lane) * KTPITCH + 2048] = pack2(a, b);
    }
    const float v0 = nv[lane], v1 = nv[lane + 32];
    unsigned* base = g_VtP + ((size_t)bh * VROWSP + 1024) * 64;
    base[lane]      = pack2(v0, 0.f);
    base[lane + 32] = pack2(v1, 0.f);
}

// ---------------- flash attention: 3-stage cp.async fills -----------------------
#define ABQ 128
#define ABK 64
#define ANT ((KVLEN + ABK - 1) / ABK)   /* 33 */
#define KTLD 72
#define VLD  72
#define AST_W (32 * KTLD + 32 * VLD)    /* 4608 words per stage */

#define ATT_SMEM (3 * AST_W * 4)        /* 55296 B */

__global__ void __launch_bounds__(256, 2) attn_mma_kernel() {
    extern __shared__ unsigned ash[];
    const unsigned asb = (unsigned)__cvta_generic_to_shared(ash);

    const int tid  = threadIdx.x;
    const int warp = tid >> 5;
    const int lane = tid & 31;
    const int r = lane >> 2;
    const int c = lane & 3;
    const int bh = blockIdx.y;
    const int qt = blockIdx.x;
    const int m0 = warp * 16;

    const unsigned* QgP = g_QP + ((size_t)bh * SEQ + (size_t)qt * ABQ + m0) * 32;
    unsigned qh[4][4];
    #pragma unroll
    for (int s = 0; s < 4; s++) {
        qh[s][0] = QgP[(size_t)r * 32 + s * 8 + c];
        qh[s][1] = QgP[(size_t)(r + 8) * 32 + s * 8 + c];
        qh[s][2] = QgP[(size_t)r * 32 + s * 8 + c + 4];
        qh[s][3] = QgP[(size_t)(r + 8) * 32 + s * 8 + c + 4];
    }

    float oacc[8][4];
    #pragma unroll
    for (int nt = 0; nt < 8; nt++)
        #pragma unroll
        for (int j = 0; j < 4; j++) oacc[nt][j] = 0.f;
    float mrow0 = -1e30f, mrow1 = -1e30f, lrow0 = 0.f, lrow1 = 0.f;

    const unsigned* KtG = g_KtP + ((size_t)bh * 32 + (tid >> 3)) * KTPITCH + (tid & 7) * 8;
    const unsigned* VtG = g_VtP + ((size_t)bh * VROWSP + (tid >> 3)) * 64 + (tid & 7) * 8;
    const unsigned koff = ((tid >> 3) * KTLD + (tid & 7) * 8) * 4;
    const unsigned voff = (32 * KTLD + (tid >> 3) * VLD + (tid & 7) * 8) * 4;

    auto fill_async = [&](int kt) {
        const unsigned st = asb + ((kt % 3) * AST_W) * 4;
        const int kvbase = kt * ABK;
        cp_async16(st + koff,      KtG + kvbase);
        cp_async16(st + koff + 16, KtG + kvbase + 4);
        const unsigned* vp = VtG + (size_t)(kt * 32) * 64;
        cp_async16(st + voff,      vp);
        cp_async16(st + voff + 16, vp + 4);
    };

    fill_async(0);
    cp_commit();
    fill_async(1);
    cp_commit();

    for (int kt = 0; kt < ANT; kt++) {
        const int kvbase = kt * ABK;
        if (kt + 1 < ANT) cp_wait1(); else cp_wait0();
        __syncthreads();
        if (kt + 2 < ANT) { fill_async(kt + 2); cp_commit(); }

        const unsigned* KtH = ash + (kt % 3) * AST_W;
        const unsigned* VH  = KtH + 32 * KTLD;

        float sa[8][4];
        #pragma unroll
        for (int nt = 0; nt < 8; nt++)
            #pragma unroll
            for (int j = 0; j < 4; j++) sa[nt][j] = 0.f;

        #pragma unroll
        for (int s = 0; s < 4; s++) {
            #pragma unroll
            for (int nt = 0; nt < 8; nt++) {
                unsigned bfh[2];
                bfh[0] = KtH[(8 * s + c) * KTLD + nt * 8 + r];
                bfh[1] = KtH[(8 * s + c + 4) * KTLD + nt * 8 + r];
                mma_f16(sa[nt], qh[s], bfh);
            }
        }

        float tmax0 = -1e30f, tmax1 = -1e30f;
        #pragma unroll
        for (int nt = 0; nt < 8; nt++) {
            const int j0 = kvbase + nt * 8 + 2 * c;
            if (j0 >= KVLEN)     { sa[nt][0] = -1e30f; sa[nt][2] = -1e30f; }
            if (j0 + 1 >= KVLEN) { sa[nt][1] = -1e30f; sa[nt][3] = -1e30f; }
            tmax0 = fmaxf(tmax0, fmaxf(sa[nt][0], sa[nt][1]));
            tmax1 = fmaxf(tmax1, fmaxf(sa[nt][2], sa[nt][3]));
        }
        tmax0 = fmaxf(tmax0, __shfl_xor_sync(0xFFFFFFFFu, tmax0, 1));
        tmax0 = fmaxf(tmax0, __shfl_xor_sync(0xFFFFFFFFu, tmax0, 2));
        tmax1 = fmaxf(tmax1, __shfl_xor_sync(0xFFFFFFFFu, tmax1, 1));
        tmax1 = fmaxf(tmax1, __shfl_xor_sync(0xFFFFFFFFu, tmax1, 2));

        const float mnew0 = fmaxf(mrow0, tmax0);
        const float mnew1 = fmaxf(mrow1, tmax1);
        const float cf0 = __expf(mrow0 - mnew0);
        const float cf1 = __expf(mrow1 - mnew1);
        mrow0 = mnew0; mrow1 = mnew1;

        unsigned pfrag[8][2];
        float psum0 = 0.f, psum1 = 0.f;
        #pragma unroll
        for (int nt = 0; nt < 8; nt++) {
            const float p0 = __expf(sa[nt][0] - mnew0);
            const float p1 = __expf(sa[nt][1] - mnew0);
            const float p2 = __expf(sa[nt][2] - mnew1);
            const float p3 = __expf(sa[nt][3] - mnew1);
            psum0 += p0 + p1;
            psum1 += p2 + p3;
            pfrag[nt][0] = pack2(p0, p1);
            pfrag[nt][1] = pack2(p2, p3);
        }
        psum0 += __shfl_xor_sync(0xFFFFFFFFu, psum0, 1);
        psum0 += __shfl_xor_sync(0xFFFFFFFFu, psum0, 2);
        psum1 += __shfl_xor_sync(0xFFFFFFFFu, psum1, 1);
        psum1 += __shfl_xor_sync(0xFFFFFFFFu, psum1, 2);
        lrow0 = lrow0 * cf0 + psum0;
        lrow1 = lrow1 * cf1 + psum1;

        #pragma unroll
        for (int nt = 0; nt < 8; nt++) {
            oacc[nt][0] *= cf0; oacc[nt][1] *= cf0;
            oacc[nt][2] *= cf1; oacc[nt][3] *= cf1;
        }

        #pragma unroll
        for (int s = 0; s < 4; s++) {
            unsigned pa[4];
            pa[0] = pfrag[2 * s][0];
            pa[1] = pfrag[2 * s][1];
            pa[2] = pfrag[2 * s + 1][0];
            pa[3] = pfrag[2 * s + 1][1];
            #pragma unroll
            for (int nt = 0; nt < 8; nt++) {
                unsigned vfh[2];
                vfh[0] = VH[(8 * s + c) * VLD + nt * 8 + r];
                vfh[1] = VH[(8 * s + c + 4) * VLD + nt * 8 + r];
                mma_f16(oacc[nt], pa, vfh);
            }
        }
    }

    const float li0 = 1.f / lrow0;
    const float li1 = 1.f / lrow1;
    const int bb = bh >> 4, h = bh & 15;
    const int row0 = qt * ABQ + m0 + r;
    #pragma unroll
    for (int nt = 0; nt < 8; nt++) {
        const size_t wi0 = (size_t)(bb * SEQ + row0) * (INNER / 2) + h * 32 + nt * 4 + c;
        const size_t wi1 = (size_t)(bb * SEQ + row0 + 8) * (INNER / 2) + h * 32 + nt * 4 + c;
        g_aoH[wi0] = pack2(oacc[nt][0] * li0, oacc[nt][1] * li0);
        g_aoH[wi1] = pack2(oacc[nt][2] * li1, oacc[nt][3] * li1);
    }
}

// ---------------- launch ------------------------------------------------------
extern "C" void kernel_launch(void* const* d_in, const int* in_sizes, int n_in,
                              void* d_out, int out_size) {
    const float* x       = (const float*)d_in[0];
    const float* gamma   = (const float*)d_in[1];
    const float* beta    = (const float*)d_in[2];
    const float* null_kv = (const float*)d_in[3];
    const float* Wq      = (const float*)d_in[4];
    const float* Wkv     = (const float*)d_in[5];
    const float* q_scale = (const float*)d_in[6];
    const float* k_scale = (const float*)d_in[7];
    const float* Wo      = (const float*)d_in[8];
    float* out = (float*)d_out;

    cudaFuncSetAttribute(gemm_qkv_kernel, cudaFuncAttributeMaxDynamicSharedMemorySize, GEMM_SMEM);
    cudaFuncSetAttribute(gemm_o_kernel,   cudaFuncAttributeMaxDynamicSharedMemorySize, GEMM_SMEM);
    cudaFuncSetAttribute(attn_mma_kernel, cudaFuncAttributeMaxDynamicSharedMemorySize, ATT_SMEM);

    pack_all<<<1024, 256>>>(Wq, Wkv, Wo);
    ln_kernel<<<TOKENS, 256>>>(x, gamma, beta);
    null_prep<<<BATCH * HEADS, 32>>>(null_kv, k_scale);
    gemm_qkv_kernel<<<dim3(NQKV / 128, TOKENS / 128), 256, GEMM_SMEM>>>(q_scale, k_scale);
    attn_mma_kernel<<<dim3(SEQ / ABQ, BATCH * HEADS), 256, ATT_SMEM>>>();
    gemm_o_kernel<<<dim3(DIM / 128, TOKENS / 128), 256, GEMM_SMEM>>>(out);
}